// round 3
// baseline (speedup 1.0000x reference)
#include <cuda_runtime.h>
#include <math.h>

#define BB 2
#define SS 2048
#define DD 1024
#define HH 16
#define DHH 64

// ---------------- scratch (device globals; no allocation allowed) ----------------
__device__ float g_qh[BB*HH*SS*DHH];     // [B,H,S,DH]
__device__ float g_kh[BB*HH*SS*DHH];     // [B,H,S,DH]
__device__ float g_vproj[BB*SS*DHH];     // [B,S,DH]
__device__ float g_oh[BB*HH*SS*DHH];     // per-head attention outputs
__device__ float g_mean[BB*SS*DHH];      // head-mean
__device__ float g_m[BB*HH*SS];          // row max
__device__ float g_l[BB*HH*SS];          // row sumexp

// ---------------- kernel 1: projections (33 GEMM tasks) ----------------
// C[s,e] = sum_d X[s,d] * W[e,d] + bias[e];  M=2048, N=64, K=1024
__global__ __launch_bounds__(256) void proj_kernel(
    const float* __restrict__ q, const float* __restrict__ k, const float* __restrict__ v,
    const float* __restrict__ Wq, const float* __restrict__ bq,
    const float* __restrict__ Wk, const float* __restrict__ bk,
    const float* __restrict__ Wv, const float* __restrict__ bv)
{
    __shared__ float xs[32][68];   // xs[d][s] (transposed X tile)
    __shared__ float wsm[32][68];  // wsm[d][e] (transposed W tile)

    int task = blockIdx.z;
    int b = blockIdx.y;
    int s0 = blockIdx.x * 64;

    const float* X; const float* W; const float* bias; float* out;
    if (task < HH) {
        X = q + (size_t)b*SS*DD; W = Wq + (size_t)task*DHH*DD; bias = bq + task*DHH;
        out = g_qh + ((size_t)(b*HH + task) * SS) * DHH;
    } else if (task < 2*HH) {
        int h = task - HH;
        X = k + (size_t)b*SS*DD; W = Wk + (size_t)h*DHH*DD; bias = bk + h*DHH;
        out = g_kh + ((size_t)(b*HH + h) * SS) * DHH;
    } else {
        X = v + (size_t)b*SS*DD; W = Wv; bias = bv;
        out = g_vproj + (size_t)b*SS*DHH;
    }

    int tid = threadIdx.x;
    int ty = tid >> 4, tx = tid & 15;
    int lr = tid >> 2;            // 0..63
    int ld = (tid & 3) * 8;       // 0,8,16,24

    float acc[4][4];
    #pragma unroll
    for (int i = 0; i < 4; i++)
        #pragma unroll
        for (int j = 0; j < 4; j++) acc[i][j] = 0.f;

    for (int d0 = 0; d0 < DD; d0 += 32) {
        float4 xa = *(const float4*)&X[(size_t)(s0+lr)*DD + d0 + ld];
        float4 xb = *(const float4*)&X[(size_t)(s0+lr)*DD + d0 + ld + 4];
        float4 wa = *(const float4*)&W[(size_t)lr*DD + d0 + ld];
        float4 wb = *(const float4*)&W[(size_t)lr*DD + d0 + ld + 4];
        __syncthreads();
        xs[ld+0][lr]=xa.x; xs[ld+1][lr]=xa.y; xs[ld+2][lr]=xa.z; xs[ld+3][lr]=xa.w;
        xs[ld+4][lr]=xb.x; xs[ld+5][lr]=xb.y; xs[ld+6][lr]=xb.z; xs[ld+7][lr]=xb.w;
        wsm[ld+0][lr]=wa.x; wsm[ld+1][lr]=wa.y; wsm[ld+2][lr]=wa.z; wsm[ld+3][lr]=wa.w;
        wsm[ld+4][lr]=wb.x; wsm[ld+5][lr]=wb.y; wsm[ld+6][lr]=wb.z; wsm[ld+7][lr]=wb.w;
        __syncthreads();
        #pragma unroll 8
        for (int kk = 0; kk < 32; kk++) {
            float4 xf = *(const float4*)&xs[kk][ty*4];
            float4 wf = *(const float4*)&wsm[kk][tx*4];
            float xr[4] = {xf.x, xf.y, xf.z, xf.w};
            float wr[4] = {wf.x, wf.y, wf.z, wf.w};
            #pragma unroll
            for (int i = 0; i < 4; i++)
                #pragma unroll
                for (int j = 0; j < 4; j++)
                    acc[i][j] += xr[i] * wr[j];
        }
    }

    float4 b4 = *(const float4*)&bias[tx*4];
    float br[4] = {b4.x, b4.y, b4.z, b4.w};
    #pragma unroll
    for (int i = 0; i < 4; i++) {
        float4 o;
        o.x = acc[i][0] + br[0]; o.y = acc[i][1] + br[1];
        o.z = acc[i][2] + br[2]; o.w = acc[i][3] + br[3];
        *(float4*)&out[(size_t)(s0 + ty*4 + i)*DHH + tx*4] = o;
    }
}

// ---------------- kernel 2: attention (raw scores out + online softmax + PV) ----------------
#define ST 68
__global__ __launch_bounds__(256) void attn_kernel(float* __restrict__ attn_out)
{
    extern __shared__ float sm[];
    float* qs = sm;               // qs[e*ST + r]
    float* ks = sm + 64*ST;       // ks[e*ST + c]
    float* vs = sm + 2*64*ST;     // vs[c*ST + e]
    float* ps = sm + 3*64*ST;     // ps[c*ST + r]

    int qi = (int)(gridDim.x - 1 - blockIdx.x);   // big tiles first (wave balance)
    int h = blockIdx.y, b = blockIdx.z;
    int s0 = qi * 64;
    int tid = threadIdx.x;
    int ty = tid >> 4, tx = tid & 15;
    int lr = tid >> 2;            // 0..63
    int le = (tid & 3) * 16;      // 0,16,32,48

    size_t bh = (size_t)(b*HH + h);
    const float* Q  = g_qh + bh * SS * DHH;
    const float* Kp = g_kh + bh * SS * DHH;
    const float* V  = g_vproj + (size_t)b * SS * DHH;

    // load Q tile transposed
    #pragma unroll
    for (int i = 0; i < 16; i += 4) {
        float4 f = *(const float4*)&Q[(size_t)(s0+lr)*DHH + le + i];
        qs[(le+i+0)*ST + lr] = f.x;
        qs[(le+i+1)*ST + lr] = f.y;
        qs[(le+i+2)*ST + lr] = f.z;
        qs[(le+i+3)*ST + lr] = f.w;
    }

    float m_run[4], l_run[4], acc[4][4];
    int srow[4];
    #pragma unroll
    for (int i = 0; i < 4; i++) {
        m_run[i] = -INFINITY; l_run[i] = 0.f;
        srow[i] = s0 + ty*4 + i;
        #pragma unroll
        for (int j = 0; j < 4; j++) acc[i][j] = 0.f;
    }

    for (int j = 0; j <= qi; j++) {
        int t0 = j * 64;
        __syncthreads();   // previous PV / Q load complete before overwrite
        #pragma unroll
        for (int i = 0; i < 16; i += 4) {
            float4 f = *(const float4*)&Kp[(size_t)(t0+lr)*DHH + le + i];
            ks[(le+i+0)*ST + lr] = f.x;
            ks[(le+i+1)*ST + lr] = f.y;
            ks[(le+i+2)*ST + lr] = f.z;
            ks[(le+i+3)*ST + lr] = f.w;
            float4 g = *(const float4*)&V[(size_t)(t0+lr)*DHH + le + i];
            *(float4*)&vs[lr*ST + le + i] = g;
        }
        __syncthreads();

        float sreg[4][4];
        #pragma unroll
        for (int i = 0; i < 4; i++)
            #pragma unroll
            for (int jj = 0; jj < 4; jj++) sreg[i][jj] = 0.f;

        #pragma unroll 16
        for (int e = 0; e < 64; e++) {
            float4 qf = *(const float4*)&qs[e*ST + ty*4];
            float4 kf = *(const float4*)&ks[e*ST + tx*4];
            float qr[4] = {qf.x, qf.y, qf.z, qf.w};
            float kr[4] = {kf.x, kf.y, kf.z, kf.w};
            #pragma unroll
            for (int i = 0; i < 4; i++)
                #pragma unroll
                for (int jj = 0; jj < 4; jj++)
                    sreg[i][jj] += qr[i] * kr[jj];
        }

        bool diag = (j == qi);
        #pragma unroll
        for (int i = 0; i < 4; i++) {
            #pragma unroll
            for (int jj = 0; jj < 4; jj++) sreg[i][jj] *= 0.125f;  // 1/sqrt(64)

            // raw (unnormalized) score write; norm pass fixes it up
            float4 w;
            w.x = sreg[i][0]; w.y = sreg[i][1]; w.z = sreg[i][2]; w.w = sreg[i][3];
            *(float4*)&attn_out[(((size_t)b*SS + srow[i])*HH + h)*SS + t0 + tx*4] = w;

            bool vld[4];
            #pragma unroll
            for (int jj = 0; jj < 4; jj++)
                vld[jj] = (!diag) || (t0 + tx*4 + jj <= srow[i]);

            float mx = -INFINITY;
            #pragma unroll
            for (int jj = 0; jj < 4; jj++) if (vld[jj]) mx = fmaxf(mx, sreg[i][jj]);
            #pragma unroll
            for (int off = 8; off > 0; off >>= 1)
                mx = fmaxf(mx, __shfl_xor_sync(0xffffffffu, mx, off, 16));

            float mnew = fmaxf(m_run[i], mx);
            float fac = expf(m_run[i] - mnew);
            m_run[i] = mnew;

            float psum = 0.f;
            float pv[4];
            #pragma unroll
            for (int jj = 0; jj < 4; jj++) {
                pv[jj] = vld[jj] ? expf(sreg[i][jj] - mnew) : 0.f;
                psum += pv[jj];
            }
            #pragma unroll
            for (int off = 8; off > 0; off >>= 1)
                psum += __shfl_xor_sync(0xffffffffu, psum, off, 16);
            l_run[i] = l_run[i] * fac + psum;

            #pragma unroll
            for (int jj = 0; jj < 4; jj++) acc[i][jj] *= fac;
            #pragma unroll
            for (int jj = 0; jj < 4; jj++)
                ps[(tx*4+jj)*ST + ty*4 + i] = pv[jj];
        }
        __syncthreads();

        #pragma unroll 16
        for (int c = 0; c < 64; c++) {
            float4 pf = *(const float4*)&ps[c*ST + ty*4];
            float4 vf = *(const float4*)&vs[c*ST + tx*4];
            float pr[4] = {pf.x, pf.y, pf.z, pf.w};
            float vr[4] = {vf.x, vf.y, vf.z, vf.w};
            #pragma unroll
            for (int i = 0; i < 4; i++)
                #pragma unroll
                for (int jj = 0; jj < 4; jj++)
                    acc[i][jj] += pr[i] * vr[jj];
        }
    }

    float* Oh = g_oh + bh * SS * DHH;
    #pragma unroll
    for (int i = 0; i < 4; i++) {
        float linv = 1.f / l_run[i];
        float4 o;
        o.x = acc[i][0]*linv; o.y = acc[i][1]*linv;
        o.z = acc[i][2]*linv; o.w = acc[i][3]*linv;
        *(float4*)&Oh[(size_t)srow[i]*DHH + tx*4] = o;
    }
    if (tx == 0) {
        #pragma unroll
        for (int i = 0; i < 4; i++) {
            g_m[bh*SS + srow[i]] = m_run[i];
            g_l[bh*SS + srow[i]] = l_run[i];
        }
    }
}

// ---------------- kernel 3: normalize raw scores -> probabilities, zero masked ----------------
__global__ __launch_bounds__(256) void norm_kernel(float* __restrict__ attn)
{
    int row = blockIdx.x;                 // 0..B*S*H-1
    int h = row % HH;
    int s = (row / HH) % SS;
    int b = row / (HH * SS);
    size_t base = (size_t)row * SS;
    int mi = (b*HH + h)*SS + s;
    float m = g_m[mi];
    float linv = 1.f / g_l[mi];

    int tid = threadIdx.x;
    #pragma unroll
    for (int i = 0; i < 2; i++) {
        int t0 = (tid + i*256) * 4;
        float4* p = (float4*)&attn[base + t0];
        float4 r;
        if (t0 + 3 <= s) {
            r = *p;
            r.x = expf(r.x - m) * linv;
            r.y = expf(r.y - m) * linv;
            r.z = expf(r.z - m) * linv;
            r.w = expf(r.w - m) * linv;
        } else if (t0 > s) {
            r.x = 0.f; r.y = 0.f; r.z = 0.f; r.w = 0.f;
        } else {
            r = *p;
            r.x = (t0+0 <= s) ? expf(r.x - m) * linv : 0.f;
            r.y = (t0+1 <= s) ? expf(r.y - m) * linv : 0.f;
            r.z = (t0+2 <= s) ? expf(r.z - m) * linv : 0.f;
            r.w = (t0+3 <= s) ? expf(r.w - m) * linv : 0.f;
        }
        *p = r;
    }
}

// ---------------- kernel 4: mean over heads ----------------
__global__ __launch_bounds__(256) void mean_kernel()
{
    int idx = blockIdx.x * 256 + threadIdx.x;   // < B*S*DH
    int e = idx & 63;
    int s = (idx >> 6) & (SS - 1);
    int b = idx >> 17;                          // 6 + 11
    float sum = 0.f;
    #pragma unroll
    for (int h = 0; h < HH; h++)
        sum += g_oh[((size_t)(b*HH + h)*SS + s)*DHH + e];
    g_mean[idx] = sum * (1.f / 16.f);
}

// ---------------- kernel 5: output projection with Wo ----------------
// out[s,d] = sum_e mean[s,e] * Wo[d,e];  M=2048, N=1024, K=64
__global__ __launch_bounds__(256) void outproj_kernel(const float* __restrict__ Wo,
                                                      float* __restrict__ out)
{
    __shared__ float ms[64][68];   // ms[e][r]
    __shared__ float wsm[64][68];  // wsm[e][c]
    int s0 = blockIdx.x * 64, d0 = blockIdx.y * 64, b = blockIdx.z;
    int tid = threadIdx.x;
    int ty = tid >> 4, tx = tid & 15;
    int lr = tid >> 2;
    int le = (tid & 3) * 16;

    #pragma unroll
    for (int i = 0; i < 16; i += 4) {
        float4 f = *(const float4*)&g_mean[((size_t)b*SS + s0+lr)*DHH + le + i];
        ms[le+i+0][lr] = f.x; ms[le+i+1][lr] = f.y;
        ms[le+i+2][lr] = f.z; ms[le+i+3][lr] = f.w;
        float4 g = *(const float4*)&Wo[(size_t)(d0+lr)*DHH + le + i];
        wsm[le+i+0][lr] = g.x; wsm[le+i+1][lr] = g.y;
        wsm[le+i+2][lr] = g.z; wsm[le+i+3][lr] = g.w;
    }
    __syncthreads();

    float acc[4][4];
    #pragma unroll
    for (int i = 0; i < 4; i++)
        #pragma unroll
        for (int j = 0; j < 4; j++) acc[i][j] = 0.f;

    #pragma unroll 16
    for (int e = 0; e < 64; e++) {
        float4 mf = *(const float4*)&ms[e][ty*4];
        float4 wf = *(const float4*)&wsm[e][tx*4];
        float mr[4] = {mf.x, mf.y, mf.z, mf.w};
        float wr[4] = {wf.x, wf.y, wf.z, wf.w};
        #pragma unroll
        for (int i = 0; i < 4; i++)
            #pragma unroll
            for (int j = 0; j < 4; j++)
                acc[i][j] += mr[i] * wr[j];
    }

    #pragma unroll
    for (int i = 0; i < 4; i++) {
        float4 o;
        o.x = acc[i][0]; o.y = acc[i][1]; o.z = acc[i][2]; o.w = acc[i][3];
        *(float4*)&out[(size_t)b*SS*DD + (size_t)(s0 + ty*4 + i)*DD + d0 + tx*4] = o;
    }
}

// ---------------- launch ----------------
extern "C" void kernel_launch(void* const* d_in, const int* in_sizes, int n_in,
                              void* d_out, int out_size)
{
    (void)in_sizes; (void)n_in; (void)out_size;
    const float* q  = (const float*)d_in[0];
    const float* k  = (const float*)d_in[1];
    const float* v  = (const float*)d_in[2];
    // d_in[3] = mask (causal, computed analytically; unused)
    const float* Wv = (const float*)d_in[4];
    const float* bv = (const float*)d_in[5];
    const float* Wq = (const float*)d_in[6];
    const float* bq = (const float*)d_in[7];
    const float* Wk = (const float*)d_in[8];
    const float* bk = (const float*)d_in[9];
    const float* Wo = (const float*)d_in[10];

    float* out  = (float*)d_out;
    float* attn = out + (size_t)BB*SS*DD;   // [B,S,H,S] after [B,S,D]

    const int attn_smem = 4 * 64 * ST * (int)sizeof(float);  // 69632 B
    cudaFuncSetAttribute(attn_kernel, cudaFuncAttributeMaxDynamicSharedMemorySize, attn_smem);

    proj_kernel<<<dim3(SS/64, BB, 2*HH + 1), 256>>>(q, k, v, Wq, bq, Wk, bk, Wv, bv);
    attn_kernel<<<dim3(SS/64, HH, BB), 256, attn_smem>>>(attn);
    norm_kernel<<<BB*SS*HH, 256>>>(attn);
    mean_kernel<<<BB*SS*DHH/256, 256>>>();
    outproj_kernel<<<dim3(SS/64, DD/64, BB), 256>>>(Wo, out);
}

// round 5
// speedup vs baseline: 1.6696x; 1.6696x over previous
#include <cuda_runtime.h>
#include <cuda_bf16.h>
#include <math.h>

#define BB 2
#define SS 2048
#define DD 1024
#define HH 16
#define DHH 64

// ---------------- scratch ----------------
__device__ __nv_bfloat16 g_qh_h[BB*HH*SS*DHH];
__device__ __nv_bfloat16 g_qh_l[BB*HH*SS*DHH];
__device__ __nv_bfloat16 g_kh_h[BB*HH*SS*DHH];
__device__ __nv_bfloat16 g_kh_l[BB*HH*SS*DHH];
__device__ __nv_bfloat16 g_vT_h[BB*DHH*SS];   // [b, e, t]
__device__ __nv_bfloat16 g_vT_l[BB*DHH*SS];
__device__ float g_oh[BB*HH*SS*DHH];
__device__ float g_mean[BB*SS*DHH];

// ---------------- helpers ----------------
__device__ __forceinline__ unsigned smem_u32(const void* p) {
    unsigned a;
    asm("{ .reg .u64 t; cvta.to.shared.u64 t, %1; cvt.u32.u64 %0, t; }" : "=r"(a) : "l"(p));
    return a;
}

__device__ __forceinline__ void sts64(unsigned addr, unsigned long long v) {
    asm volatile("st.shared.b64 [%0], %1;" :: "r"(addr), "l"(v) : "memory");
}

__device__ __forceinline__ void ldsm4(unsigned addr, unsigned& r0, unsigned& r1,
                                      unsigned& r2, unsigned& r3) {
    asm volatile("ldmatrix.sync.aligned.m8n8.x4.shared.b16 {%0,%1,%2,%3}, [%4];"
        : "=r"(r0), "=r"(r1), "=r"(r2), "=r"(r3) : "r"(addr));
}

__device__ __forceinline__ void mma16816(float* c, const unsigned* a, const unsigned* b) {
    asm volatile("mma.sync.aligned.m16n8k16.row.col.f32.bf16.bf16.f32 "
        "{%0,%1,%2,%3}, {%4,%5,%6,%7}, {%8,%9}, {%0,%1,%2,%3};"
        : "+f"(c[0]), "+f"(c[1]), "+f"(c[2]), "+f"(c[3])
        : "r"(a[0]), "r"(a[1]), "r"(a[2]), "r"(a[3]), "r"(b[0]), "r"(b[1]));
}

__device__ __forceinline__ void split2(float a, float b, unsigned& hi, unsigned& lo) {
    __nv_bfloat162 h = __float22bfloat162_rn(make_float2(a, b));
    float2 hf = __bfloat1622float2(h);
    __nv_bfloat162 l = __float22bfloat162_rn(make_float2(a - hf.x, b - hf.y));
    hi = *(unsigned*)&h; lo = *(unsigned*)&l;
}

// rows x 64 fp32 (row stride ld elems, col offset k0) -> split -> smem hi/lo, 144B row stride
__device__ __forceinline__ void load_f32_split(const float* __restrict__ src, int rows,
                                               size_t ld, int k0, unsigned sh, unsigned sl,
                                               int tid, int nthr) {
    int nch = rows * 16;
    for (int c = tid; c < nch; c += nthr) {
        int row = c >> 4, cg = c & 15;
        float4 f = *(const float4*)&src[(size_t)row * ld + k0 + cg * 4];
        unsigned h0, l0, h1, l1;
        split2(f.x, f.y, h0, l0);
        split2(f.z, f.w, h1, l1);
        unsigned off = (unsigned)(row * 144 + cg * 8);
        sts64(sh + off, ((unsigned long long)h1 << 32) | h0);
        sts64(sl + off, ((unsigned long long)l1 << 32) | l0);
    }
}

// rows x 64 bf16 (contiguous rows of 64) -> smem, 144B row stride
__device__ __forceinline__ void load_bf16_pair(const __nv_bfloat16* __restrict__ srcH,
                                               const __nv_bfloat16* __restrict__ srcL,
                                               int rows, unsigned sh, unsigned sl,
                                               int tid, int nthr) {
    const unsigned long long* pH = (const unsigned long long*)srcH;
    const unsigned long long* pL = (const unsigned long long*)srcL;
    int nch = rows * 16;
    for (int c = tid; c < nch; c += nthr) {
        int row = c >> 4, cg = c & 15;
        unsigned off = (unsigned)(row * 144 + cg * 8);
        sts64(sh + off, pH[c]);
        sts64(sl + off, pL[c]);
    }
}

// 64 x 64 bf16, row stride ld elems, col offset t0 -> smem, 144B row stride
__device__ __forceinline__ void load_bf16_strided(const __nv_bfloat16* __restrict__ srcH,
                                                  const __nv_bfloat16* __restrict__ srcL,
                                                  size_t ld, int t0, unsigned sh, unsigned sl,
                                                  int tid, int nthr) {
    for (int c = tid; c < 64 * 16; c += nthr) {
        int row = c >> 4, cg = c & 15;
        unsigned long long h = *(const unsigned long long*)&srcH[(size_t)row * ld + t0 + cg * 4];
        unsigned long long l = *(const unsigned long long*)&srcL[(size_t)row * ld + t0 + cg * 4];
        unsigned off = (unsigned)(row * 144 + cg * 8);
        sts64(sh + off, h);
        sts64(sl + off, l);
    }
}

// ---------------- kernel 1: projections (HMMA) ----------------
// out[s,e] = sum_d X[s,d]*W[e,d] + bias[e]; block: M=128, N=64, K=1024 in 16 chunks
__global__ __launch_bounds__(256) void proj_mma(
    const float* __restrict__ q, const float* __restrict__ k, const float* __restrict__ v,
    const float* __restrict__ Wq, const float* __restrict__ bq,
    const float* __restrict__ Wk, const float* __restrict__ bk,
    const float* __restrict__ Wv, const float* __restrict__ bv)
{
    extern __shared__ char sm_[];
    unsigned sb = smem_u32(sm_);
    const unsigned AH = sb, AL = sb + 18432, BH = sb + 36864, BL = sb + 46080;

    int tid = threadIdx.x, w = tid >> 5, lane = tid & 31;
    int mt = blockIdx.x, b = blockIdx.y, task = blockIdx.z;
    int s0 = mt * 128;

    const float *X, *W, *bias;
    __nv_bfloat16 *dstH = 0, *dstL = 0;
    int isV = 0;
    if (task < HH) {
        X = q + (size_t)b*SS*DD; W = Wq + (size_t)task*DHH*DD; bias = bq + task*DHH;
        dstH = g_qh_h + (size_t)(b*HH + task)*SS*DHH;
        dstL = g_qh_l + (size_t)(b*HH + task)*SS*DHH;
    } else if (task < 2*HH) {
        int h = task - HH;
        X = k + (size_t)b*SS*DD; W = Wk + (size_t)h*DHH*DD; bias = bk + h*DHH;
        dstH = g_kh_h + (size_t)(b*HH + h)*SS*DHH;
        dstL = g_kh_l + (size_t)(b*HH + h)*SS*DHH;
    } else {
        X = v + (size_t)b*SS*DD; W = Wv; bias = bv; isV = 1;
    }

    float cf[8][4];
    #pragma unroll
    for (int nf = 0; nf < 8; nf++)
        #pragma unroll
        for (int i = 0; i < 4; i++) cf[nf][i] = 0.f;

    int lrow = lane & 15;
    unsigned lcol16 = (unsigned)(lane >> 4) * 16;
    unsigned aBaseH = AH + (unsigned)(16*w + lrow) * 144 + lcol16;
    unsigned aBaseL = AL + (unsigned)(16*w + lrow) * 144 + lcol16;

    for (int c = 0; c < 16; c++) {
        __syncthreads();
        load_f32_split(X + (size_t)s0 * DD, 128, DD, c * 64, AH, AL, tid, 256);
        load_f32_split(W, 64, DD, c * 64, BH, BL, tid, 256);
        __syncthreads();
        #pragma unroll
        for (int ks = 0; ks < 4; ks++) {
            unsigned kb = (unsigned)ks * 32;
            unsigned aH[4], aL[4];
            ldsm4(aBaseH + kb, aH[0], aH[1], aH[2], aH[3]);
            ldsm4(aBaseL + kb, aL[0], aL[1], aL[2], aL[3]);
            unsigned bh[8][2], bl[8][2];
            #pragma unroll
            for (int nt2 = 0; nt2 < 4; nt2++) {
                unsigned r0, r1, r2, r3;
                unsigned boff = (unsigned)(nt2*16 + lrow) * 144 + lcol16 + kb;
                ldsm4(BH + boff, r0, r1, r2, r3);
                bh[2*nt2][0] = r0; bh[2*nt2][1] = r2;
                bh[2*nt2+1][0] = r1; bh[2*nt2+1][1] = r3;
                ldsm4(BL + boff, r0, r1, r2, r3);
                bl[2*nt2][0] = r0; bl[2*nt2][1] = r2;
                bl[2*nt2+1][0] = r1; bl[2*nt2+1][1] = r3;
            }
            #pragma unroll
            for (int nf = 0; nf < 8; nf++) {
                mma16816(cf[nf], aH, bh[nf]);
                mma16816(cf[nf], aH, bl[nf]);
                mma16816(cf[nf], aL, bh[nf]);
            }
        }
    }

    // epilogue
    int row0 = s0 + 16*w + (lane >> 2);
    int colb = (lane & 3) * 2;
    if (!isV) {
        #pragma unroll
        for (int nf = 0; nf < 8; nf++) {
            int col = nf * 8 + colb;
            float b0 = __ldg(&bias[col]), b1 = __ldg(&bias[col + 1]);
            unsigned h, l;
            split2(cf[nf][0] + b0, cf[nf][1] + b1, h, l);
            *(unsigned*)&dstH[(size_t)row0 * DHH + col] = h;
            *(unsigned*)&dstL[(size_t)row0 * DHH + col] = l;
            split2(cf[nf][2] + b0, cf[nf][3] + b1, h, l);
            *(unsigned*)&dstH[(size_t)(row0 + 8) * DHH + col] = h;
            *(unsigned*)&dstL[(size_t)(row0 + 8) * DHH + col] = l;
        }
    } else {
        #pragma unroll
        for (int nf = 0; nf < 8; nf++) {
            int col = nf * 8 + colb;
            float b0 = __ldg(&bias[col]), b1 = __ldg(&bias[col + 1]);
            float vv[4] = {cf[nf][0] + b0, cf[nf][1] + b1, cf[nf][2] + b0, cf[nf][3] + b1};
            int rr[4] = {row0, row0, row0 + 8, row0 + 8};
            int cc[4] = {col, col + 1, col, col + 1};
            #pragma unroll
            for (int i = 0; i < 4; i++) {
                __nv_bfloat16 hb = __float2bfloat16(vv[i]);
                __nv_bfloat16 lb = __float2bfloat16(vv[i] - __bfloat162float(hb));
                g_vT_h[((size_t)b * DHH + cc[i]) * SS + rr[i]] = hb;
                g_vT_l[((size_t)b * DHH + cc[i]) * SS + rr[i]] = lb;
            }
        }
    }
}

// ---------------- kernel 2: QK^T raw scores (HMMA) ----------------
// lower-triangular 128x128 tiles; raw fp32 scores out
__global__ __launch_bounds__(256) void score_mma(float* __restrict__ attn)
{
    int x = blockIdx.x;
    int mt = (int)((sqrtf(8.f * x + 1.f) - 1.f) * 0.5f);
    while ((mt + 1) * (mt + 2) / 2 <= x) mt++;
    while (mt * (mt + 1) / 2 > x) mt--;
    int nt = x - mt * (mt + 1) / 2;
    int m0 = mt * 128, n0 = nt * 128;
    int h = blockIdx.y, b = blockIdx.z;
    int tid = threadIdx.x, w = tid >> 5, lane = tid & 31;

    extern __shared__ char sm_[];
    unsigned sb = smem_u32(sm_);
    const unsigned QH = sb, QL = sb + 18432, KH = sb + 36864, KL = sb + 55296;

    size_t bh = (size_t)(b * HH + h);
    load_bf16_pair(g_qh_h + (bh*SS + m0)*DHH, g_qh_l + (bh*SS + m0)*DHH, 128, QH, QL, tid, 256);
    load_bf16_pair(g_kh_h + (bh*SS + n0)*DHH, g_kh_l + (bh*SS + n0)*DHH, 128, KH, KL, tid, 256);
    __syncthreads();

    int mw = w >> 1, nw = w & 1;     // warp tile: 32 rows x 64 cols
    int lrow = lane & 15;
    unsigned lcol16 = (unsigned)(lane >> 4) * 16;

    float cf[2][8][4];
    #pragma unroll
    for (int mf = 0; mf < 2; mf++)
        #pragma unroll
        for (int nf = 0; nf < 8; nf++)
            #pragma unroll
            for (int i = 0; i < 4; i++) cf[mf][nf][i] = 0.f;

    #pragma unroll
    for (int ks = 0; ks < 4; ks++) {
        unsigned kb = (unsigned)ks * 32;
        unsigned aH[2][4], aL[2][4];
        #pragma unroll
        for (int mf = 0; mf < 2; mf++) {
            unsigned aoff = (unsigned)(mw*32 + mf*16 + lrow) * 144 + lcol16 + kb;
            ldsm4(QH + aoff, aH[mf][0], aH[mf][1], aH[mf][2], aH[mf][3]);
            ldsm4(QL + aoff, aL[mf][0], aL[mf][1], aL[mf][2], aL[mf][3]);
        }
        unsigned bh2[8][2], bl2[8][2];
        #pragma unroll
        for (int nt2 = 0; nt2 < 4; nt2++) {
            unsigned boff = (unsigned)(nw*64 + nt2*16 + lrow) * 144 + lcol16 + kb;
            unsigned r0, r1, r2, r3;
            ldsm4(KH + boff, r0, r1, r2, r3);
            bh2[2*nt2][0] = r0; bh2[2*nt2][1] = r2;
            bh2[2*nt2+1][0] = r1; bh2[2*nt2+1][1] = r3;
            ldsm4(KL + boff, r0, r1, r2, r3);
            bl2[2*nt2][0] = r0; bl2[2*nt2][1] = r2;
            bl2[2*nt2+1][0] = r1; bl2[2*nt2+1][1] = r3;
        }
        #pragma unroll
        for (int mf = 0; mf < 2; mf++)
            #pragma unroll
            for (int nf = 0; nf < 8; nf++) {
                mma16816(cf[mf][nf], aH[mf], bh2[nf]);
                mma16816(cf[mf][nf], aH[mf], bl2[nf]);
                mma16816(cf[mf][nf], aL[mf], bh2[nf]);
            }
    }

    // stage through smem for coalesced writes (stride 132 floats)
    __syncthreads();
    int rbase = mw * 32 + (lane >> 2);
    int cbase = nw * 64 + (lane & 3) * 2;
    #pragma unroll
    for (int mf = 0; mf < 2; mf++)
        #pragma unroll
        for (int nf = 0; nf < 8; nf++) {
            int r = rbase + mf * 16, c = cbase + nf * 8;
            *(float2*)(sm_ + ((size_t)r * 132 + c) * 4) = make_float2(cf[mf][nf][0], cf[mf][nf][1]);
            *(float2*)(sm_ + ((size_t)(r + 8) * 132 + c) * 4) = make_float2(cf[mf][nf][2], cf[mf][nf][3]);
        }
    __syncthreads();

    float* dstBase = attn + (((size_t)b * SS + m0) * HH + h) * SS + n0;
    #pragma unroll
    for (int i = 0; i < 16; i++) {
        int fid = (tid + i * 256) * 4;
        int row = fid >> 7, col = fid & 127;
        float4 f = *(const float4*)(sm_ + ((size_t)row * 132 + col) * 4);
        *(float4*)(dstBase + (size_t)row * HH * SS + col) = f;
    }
}

// ---------------- kernel 3: exact row softmax (skips unwritten region) ----------------
__global__ __launch_bounds__(128) void softmax_k(float* __restrict__ attn)
{
    int row = blockIdx.x;                    // ((b*S + s)*H + h)
    int s = (row >> 4) & (SS - 1);
    float* p = attn + (size_t)row * SS;
    int tid = threadIdx.x;
    __shared__ float red[4];

    float vals[16];
    float mx = -INFINITY;
    #pragma unroll
    for (int i = 0; i < 4; i++) {
        int ci = i * 128 + tid;
        int t0 = ci * 4;
        if (t0 <= s) {
            float4 f = ((const float4*)p)[ci];
            float v0 = f.x*0.125f, v1 = f.y*0.125f, v2 = f.z*0.125f, v3 = f.w*0.125f;
            vals[i*4+0]=v0; vals[i*4+1]=v1; vals[i*4+2]=v2; vals[i*4+3]=v3;
            mx = fmaxf(mx, v0);
            if (t0+1 <= s) mx = fmaxf(mx, v1);
            if (t0+2 <= s) mx = fmaxf(mx, v2);
            if (t0+3 <= s) mx = fmaxf(mx, v3);
        } else {
            vals[i*4+0]=-INFINITY; vals[i*4+1]=-INFINITY;
            vals[i*4+2]=-INFINITY; vals[i*4+3]=-INFINITY;
        }
    }
    #pragma unroll
    for (int o = 16; o > 0; o >>= 1) mx = fmaxf(mx, __shfl_xor_sync(0xffffffffu, mx, o));
    if ((tid & 31) == 0) red[tid >> 5] = mx;
    __syncthreads();
    mx = fmaxf(fmaxf(red[0], red[1]), fmaxf(red[2], red[3]));
    __syncthreads();

    float sum = 0.f;
    #pragma unroll
    for (int i = 0; i < 4; i++) {
        int t0 = (i * 128 + tid) * 4;
        #pragma unroll
        for (int j = 0; j < 4; j++) {
            float e = (t0 + j <= s) ? expf(vals[i*4+j] - mx) : 0.f;
            vals[i*4+j] = e; sum += e;
        }
    }
    #pragma unroll
    for (int o = 16; o > 0; o >>= 1) sum += __shfl_xor_sync(0xffffffffu, sum, o);
    if ((tid & 31) == 0) red[tid >> 5] = sum;
    __syncthreads();
    float inv = 1.f / (red[0] + red[1] + red[2] + red[3]);

    #pragma unroll
    for (int i = 0; i < 4; i++) {
        int ci = i * 128 + tid;
        float4 o;
        o.x = vals[i*4+0]*inv; o.y = vals[i*4+1]*inv;
        o.z = vals[i*4+2]*inv; o.w = vals[i*4+3]*inv;
        ((float4*)p)[ci] = o;
    }
}

// ---------------- kernel 4: PV GEMM (HMMA) ----------------
// out_h[s,e] = sum_t P[b,s,h,t] * vT[b,e,t]; block M=128, N=64, K=(mt+1)*128
__global__ __launch_bounds__(256) void pv_mma(const float* __restrict__ attn)
{
    int mt = (int)(gridDim.x - 1 - blockIdx.x);
    int h = blockIdx.y, b = blockIdx.z;
    int m0 = mt * 128;
    int tid = threadIdx.x, w = tid >> 5, lane = tid & 31;

    extern __shared__ char sm_[];
    unsigned sb = smem_u32(sm_);
    const unsigned AH = sb, AL = sb + 18432, BH = sb + 36864, BL = sb + 46080;

    const float* P = attn + (((size_t)b * SS + m0) * HH + h) * SS;   // row stride HH*SS
    const __nv_bfloat16* VH = g_vT_h + (size_t)b * DHH * SS;
    const __nv_bfloat16* VL = g_vT_l + (size_t)b * DHH * SS;

    float cf[8][4];
    #pragma unroll
    for (int nf = 0; nf < 8; nf++)
        #pragma unroll
        for (int i = 0; i < 4; i++) cf[nf][i] = 0.f;

    int lrow = lane & 15;
    unsigned lcol16 = (unsigned)(lane >> 4) * 16;
    unsigned aBaseH = AH + (unsigned)(16*w + lrow) * 144 + lcol16;
    unsigned aBaseL = AL + (unsigned)(16*w + lrow) * 144 + lcol16;

    int nchunks = 2 * mt + 2;
    for (int c = 0; c < nchunks; c++) {
        __syncthreads();
        load_f32_split(P, 128, (size_t)HH * SS, c * 64, AH, AL, tid, 256);
        load_bf16_strided(VH, VL, SS, c * 64, BH, BL, tid, 256);
        __syncthreads();
        #pragma unroll
        for (int ks = 0; ks < 4; ks++) {
            unsigned kb = (unsigned)ks * 32;
            unsigned aH[4], aL[4];
            ldsm4(aBaseH + kb, aH[0], aH[1], aH[2], aH[3]);
            ldsm4(aBaseL + kb, aL[0], aL[1], aL[2], aL[3]);
            unsigned bh2[8][2], bl2[8][2];
            #pragma unroll
            for (int nt2 = 0; nt2 < 4; nt2++) {
                unsigned boff = (unsigned)(nt2*16 + lrow) * 144 + lcol16 + kb;
                unsigned r0, r1, r2, r3;
                ldsm4(BH + boff, r0, r1, r2, r3);
                bh2[2*nt2][0] = r0; bh2[2*nt2][1] = r2;
                bh2[2*nt2+1][0] = r1; bh2[2*nt2+1][1] = r3;
                ldsm4(BL + boff, r0, r1, r2, r3);
                bl2[2*nt2][0] = r0; bl2[2*nt2][1] = r2;
                bl2[2*nt2+1][0] = r1; bl2[2*nt2+1][1] = r3;
            }
            #pragma unroll
            for (int nf = 0; nf < 8; nf++) {
                mma16816(cf[nf], aH, bh2[nf]);
                mma16816(cf[nf], aH, bl2[nf]);
                mma16816(cf[nf], aL, bh2[nf]);
            }
        }
    }

    int row0 = m0 + 16*w + (lane >> 2);
    int colb = (lane & 3) * 2;
    float* dst = g_oh + ((size_t)(b * HH + h) * SS) * DHH;
    #pragma unroll
    for (int nf = 0; nf < 8; nf++) {
        int col = nf * 8 + colb;
        *(float2*)&dst[(size_t)row0 * DHH + col] = make_float2(cf[nf][0], cf[nf][1]);
        *(float2*)&dst[(size_t)(row0 + 8) * DHH + col] = make_float2(cf[nf][2], cf[nf][3]);
    }
}

// ---------------- kernel 5: mean over heads ----------------
__global__ __launch_bounds__(256) void mean_kernel()
{
    int idx = blockIdx.x * 256 + threadIdx.x;
    int e = idx & 63;
    int s = (idx >> 6) & (SS - 1);
    int b = idx >> 17;
    float sum = 0.f;
    #pragma unroll
    for (int h = 0; h < HH; h++)
        sum += g_oh[((size_t)(b*HH + h)*SS + s)*DHH + e];
    g_mean[idx] = sum * (1.f / 16.f);
}

// ---------------- kernel 6: output projection ----------------
__global__ __launch_bounds__(256) void outproj_kernel(const float* __restrict__ Wo,
                                                      float* __restrict__ out)
{
    __shared__ float ms[64][68];
    __shared__ float wsm[64][68];
    int s0 = blockIdx.x * 64, d0 = blockIdx.y * 64, b = blockIdx.z;
    int tid = threadIdx.x;
    int ty = tid >> 4, tx = tid & 15;
    int lr = tid >> 2;
    int le = (tid & 3) * 16;

    #pragma unroll
    for (int i = 0; i < 16; i += 4) {
        float4 f = *(const float4*)&g_mean[((size_t)b*SS + s0+lr)*DHH + le + i];
        ms[le+i+0][lr] = f.x; ms[le+i+1][lr] = f.y;
        ms[le+i+2][lr] = f.z; ms[le+i+3][lr] = f.w;
        float4 g = *(const float4*)&Wo[(size_t)(d0+lr)*DHH + le + i];
        wsm[le+i+0][lr] = g.x; wsm[le+i+1][lr] = g.y;
        wsm[le+i+2][lr] = g.z; wsm[le+i+3][lr] = g.w;
    }
    __syncthreads();

    float acc[4][4];
    #pragma unroll
    for (int i = 0; i < 4; i++)
        #pragma unroll
        for (int j = 0; j < 4; j++) acc[i][j] = 0.f;

    #pragma unroll 16
    for (int e = 0; e < 64; e++) {
        float4 mf = *(const float4*)&ms[e][ty*4];
        float4 wf = *(const float4*)&wsm[e][tx*4];
        float mr[4] = {mf.x, mf.y, mf.z, mf.w};
        float wr[4] = {wf.x, wf.y, wf.z, wf.w};
        #pragma unroll
        for (int i = 0; i < 4; i++)
            #pragma unroll
            for (int j = 0; j < 4; j++)
                acc[i][j] += mr[i] * wr[j];
    }

    #pragma unroll
    for (int i = 0; i < 4; i++) {
        float4 o;
        o.x = acc[i][0]; o.y = acc[i][1]; o.z = acc[i][2]; o.w = acc[i][3];
        *(float4*)&out[(size_t)b*SS*DD + (size_t)(s0 + ty*4 + i)*DD + d0 + tx*4] = o;
    }
}

// ---------------- launch ----------------
extern "C" void kernel_launch(void* const* d_in, const int* in_sizes, int n_in,
                              void* d_out, int out_size)
{
    (void)in_sizes; (void)n_in; (void)out_size;
    const float* q  = (const float*)d_in[0];
    const float* k  = (const float*)d_in[1];
    const float* v  = (const float*)d_in[2];
    const float* Wv = (const float*)d_in[4];
    const float* bv = (const float*)d_in[5];
    const float* Wq = (const float*)d_in[6];
    const float* bq = (const float*)d_in[7];
    const float* Wk = (const float*)d_in[8];
    const float* bk = (const float*)d_in[9];
    const float* Wo = (const float*)d_in[10];

    float* out  = (float*)d_out;
    float* attn = out + (size_t)BB*SS*DD;

    const int PROJ_SMEM  = 55296;
    const int SCORE_SMEM = 73728;
    const int PV_SMEM    = 55296;

    cudaFuncSetAttribute(proj_mma,  cudaFuncAttributeMaxDynamicSharedMemorySize, PROJ_SMEM);
    cudaFuncSetAttribute(score_mma, cudaFuncAttributeMaxDynamicSharedMemorySize, SCORE_SMEM);
    cudaFuncSetAttribute(pv_mma,    cudaFuncAttributeMaxDynamicSharedMemorySize, PV_SMEM);

    proj_mma<<<dim3(SS/128, BB, 2*HH + 1), 256, PROJ_SMEM>>>(q, k, v, Wq, bq, Wk, bk, Wv, bv);
    score_mma<<<dim3(136, HH, BB), 256, SCORE_SMEM>>>(attn);
    softmax_k<<<BB*SS*HH, 128>>>(attn);
    pv_mma<<<dim3(SS/128, HH, BB), 256, PV_SMEM>>>(attn);
    mean_kernel<<<BB*SS*DHH/256, 256>>>();
    outproj_kernel<<<dim3(SS/64, DD/64, BB), 256>>>(Wo, out);
}